// round 14
// baseline (speedup 1.0000x reference)
#include <cuda_runtime.h>
#include <cuda_fp16.h>
#include <cstdint>

#define BATCH 512
#define NNEG  2048
#define EDIM  256
#define KDIM  512           // int8 K = 2*E
#define KC    128           // int8 K per chunk = 128 bytes/row
#define NCH   (KDIM / KC)   // 4 chunks
#define STG   3

// Scratch: int8 operands + per-32-block fp32 scales
__device__ __align__(16) int8_t g_Aq[BATCH * KDIM];
__device__ __align__(16) int8_t g_Bq[NNEG  * KDIM];
__device__ float g_Asc[BATCH * 16];
__device__ float g_Bsc[NNEG  * 16];
__device__ float g_c[BATCH];
__device__ unsigned long long g_bar;

#define BM 64
#define BN 64
#define STAGE_BYTES 16384                  // A 8KB + B 8KB
#define SC_A (STG * STAGE_BYTES)           // 49152
#define SC_B (SC_A + 16 * 66 * 4)          // +4224
#define SM_TOTAL (SC_B + 16 * 66 * 4)      // 57600

__device__ __forceinline__ uint32_t s2u(const void* p) {
    uint32_t a;
    asm("{ .reg .u64 t; cvta.to.shared.u64 t, %1; cvt.u32.u64 %0, t; }" : "=r"(a) : "l"(p));
    return a;
}
__device__ __forceinline__ uint32_t sw128(uint32_t off) {
    return off ^ ((off >> 3) & 0x70);
}
__device__ __forceinline__ void cpasync16(uint32_t dst, const void* src) {
    asm volatile("cp.async.cg.shared.global [%0], [%1], 16;" :: "r"(dst), "l"(src));
}
__device__ __forceinline__ float wredsum(float v) {
    #pragma unroll
    for (int o = 16; o > 0; o >>= 1) v += __shfl_xor_sync(0xffffffffu, v, o);
    return v;
}
// quad (4-lane) absmax of 8 local values
__device__ __forceinline__ float quadmax8(const float* v) {
    float m = 0.f;
    #pragma unroll
    for (int i = 0; i < 8; i++) m = fmaxf(m, fabsf(v[i]));
    m = fmaxf(m, __shfl_xor_sync(0xffffffffu, m, 1));
    m = fmaxf(m, __shfl_xor_sync(0xffffffffu, m, 2));
    return m;
}
__device__ __forceinline__ uint2 pack8q(const float* v, float inv) {
    int q[8];
    #pragma unroll
    for (int i = 0; i < 8; i++) q[i] = __float2int_rn(v[i] * inv);
    uint2 u;
    u.x = (q[0] & 255) | ((q[1] & 255) << 8) | ((q[2] & 255) << 16) | ((q[3] & 255) << 24);
    u.y = (q[4] & 255) | ((q[5] & 255) << 8) | ((q[6] & 255) << 16) | ((q[7] & 255) << 24);
    return u;
}

// ---------------------------------------------------------------------------
// Fused kernel: pipelined prep+quant -> grid barrier -> IMMA GEMM (block-scaled)
// ---------------------------------------------------------------------------
__global__ void __launch_bounds__(128, 2)
fused_kernel(float* __restrict__ out,
             const float* __restrict__ head,
             const float* __restrict__ tail,
             const float* __restrict__ rel,
             const int* __restrict__ rid) {
    extern __shared__ __align__(128) char smem[];

    int tid = threadIdx.x;
    int lane = tid & 31;
    int wid = tid >> 5;                        // 0..3
    int flat = blockIdx.y * 32 + blockIdx.x;   // 0..255
    int e0 = lane * 8;
    int kb0 = lane >> 2;                       // this lane's 32-block (0..7)

    // ======== Phase 1: pipelined prep + int8 quantization ========
    {
        bool hasA = (wid < 2);
        int b  = flat * 2 + wid;
        int j0 = flat * 8 + wid;
        int j1 = j0 + 4;

        float hv[8];
        int r = 0;
        if (hasA) {
            *reinterpret_cast<float4*>(hv)     = *reinterpret_cast<const float4*>(&head[b * EDIM + e0]);
            *reinterpret_cast<float4*>(hv + 4) = *reinterpret_cast<const float4*>(&head[b * EDIM + e0 + 4]);
            r = __ldg(&rid[b]);
        }
        float tv0[8], tv1[8];
        *reinterpret_cast<float4*>(tv0)     = *reinterpret_cast<const float4*>(&tail[j0 * EDIM + e0]);
        *reinterpret_cast<float4*>(tv0 + 4) = *reinterpret_cast<const float4*>(&tail[j0 * EDIM + e0 + 4]);
        *reinterpret_cast<float4*>(tv1)     = *reinterpret_cast<const float4*>(&tail[j1 * EDIM + e0]);
        *reinterpret_cast<float4*>(tv1 + 4) = *reinterpret_cast<const float4*>(&tail[j1 * EDIM + e0 + 4]);

        float rh[8], rt[8];
        if (hasA) {
            const float* rrow = rel + (size_t)r * KDIM;
            *reinterpret_cast<float4*>(rh)     = *reinterpret_cast<const float4*>(&rrow[e0]);
            *reinterpret_cast<float4*>(rh + 4) = *reinterpret_cast<const float4*>(&rrow[e0 + 4]);
            *reinterpret_cast<float4*>(rt)     = *reinterpret_cast<const float4*>(&rrow[EDIM + e0]);
            *reinterpret_cast<float4*>(rt + 4) = *reinterpret_cast<const float4*>(&rrow[EDIM + e0 + 4]);
        }

        // B rows (covers rel latency)
        #pragma unroll
        for (int t2 = 0; t2 < 2; t2++) {
            float* tv = t2 ? tv1 : tv0;
            int j = t2 ? j1 : j0;
            float s = 0.f;
            #pragma unroll
            for (int i = 0; i < 8; i++) s += tv[i] * tv[i];
            s = wredsum(s);
            float inv = 1.f / fmaxf(sqrtf(s), 1e-12f);
            float w1[8], w2[8];
            #pragma unroll
            for (int i = 0; i < 8; i++) {
                float tn = tv[i] * inv;
                w1[i] = tn * tn;
                w2[i] = tn;
            }
            float m1 = quadmax8(w1), m2 = quadmax8(w2);
            float s1 = fmaxf(m1, 1e-20f) * (1.f / 127.f);
            float s2 = fmaxf(m2, 1e-20f) * (1.f / 127.f);
            size_t rb = (size_t)j * KDIM;
            *reinterpret_cast<uint2*>(&g_Bq[rb + e0])        = pack8q(w1, 1.f / s1);
            *reinterpret_cast<uint2*>(&g_Bq[rb + EDIM + e0]) = pack8q(w2, 1.f / s2);
            if ((lane & 3) == 0) {
                g_Bsc[j * 16 + kb0]     = s1;
                g_Bsc[j * 16 + 8 + kb0] = s2;
            }
        }

        if (hasA) {
            float s = 0.f;
            #pragma unroll
            for (int i = 0; i < 8; i++) s += hv[i] * hv[i];
            s = wredsum(s);
            float inv = 1.f / fmaxf(sqrtf(s), 1e-12f);
            float v1[8], v2[8], cs = 0.f;
            #pragma unroll
            for (int i = 0; i < 8; i++) {
                float hh = hv[i] * inv * rh[i];
                v1[i] = rt[i] * rt[i];
                v2[i] = -2.f * rt[i] * hh;
                cs += hh * hh;
            }
            float m1 = quadmax8(v1), m2 = quadmax8(v2);
            float s1 = fmaxf(m1, 1e-20f) * (1.f / 127.f);
            float s2 = fmaxf(m2, 1e-20f) * (1.f / 127.f);
            size_t ra = (size_t)b * KDIM;
            *reinterpret_cast<uint2*>(&g_Aq[ra + e0])        = pack8q(v1, 1.f / s1);
            *reinterpret_cast<uint2*>(&g_Aq[ra + EDIM + e0]) = pack8q(v2, 1.f / s2);
            if ((lane & 3) == 0) {
                g_Asc[b * 16 + kb0]     = s1;
                g_Asc[b * 16 + 8 + kb0] = s2;
            }
            cs = wredsum(cs);
            if (lane == 0) g_c[b] = cs;
        }
    }
    __threadfence();

    // ======== Phase 2: grid barrier (monotonic generation; replay-safe) ========
    __syncthreads();
    if (tid == 0) {
        unsigned long long ticket = atomicAdd(&g_bar, 1ULL);
        unsigned long long target = ((ticket >> 8) + 1) << 8;
        unsigned long long cur;
        do {
            asm volatile("ld.acquire.gpu.global.u64 %0, [%1];"
                         : "=l"(cur) : "l"(&g_bar));
            if (cur >= target) break;
            __nanosleep(64);
        } while (true);
    }
    __syncthreads();

    // ======== Phase 3: block-scaled IMMA GEMM ========
    int wm = wid & 1;
    int wn = wid >> 1;
    int bn0 = blockIdx.x * BN;
    int bm0 = blockIdx.y * BM;
    int groupID = lane >> 2;
    int tig = lane & 3;

    int er0 = bm0 + wm * 32 + groupID;
    float cpre[2][2];
    cpre[0][0] = g_c[er0];
    cpre[0][1] = g_c[er0 + 8];
    cpre[1][0] = g_c[er0 + 16];
    cpre[1][1] = g_c[er0 + 24];

    float acc[2][4][4];
    #pragma unroll
    for (int mi = 0; mi < 2; mi++)
        #pragma unroll
        for (int ni = 0; ni < 4; ni++)
            #pragma unroll
            for (int q = 0; q < 4; q++) acc[mi][ni][q] = 0.f;

    uint32_t sbase = s2u(smem);

    int aRow = (lane & 7) + ((lane >> 3) & 1) * 8;
    int aKhB = (lane >> 4) * 16;               // byte offset of k-half
    int bRowOff = ((lane >> 4) & 1) * 8 + (lane & 7);
    int bKhB    = ((lane >> 3) & 1) * 16;

    auto issue = [&](int ic) {
        if (ic < NCH) {
            uint32_t sD = sbase + (ic % STG) * STAGE_BYTES;
            int k0 = ic * KC;
            #pragma unroll
            for (int i = 0; i < 4; i++) {
                int idx = i * 128 + tid;
                int r = idx >> 3, c = idx & 7;
                cpasync16(sD + sw128(r * 128 + c * 16),
                          &g_Aq[(size_t)(bm0 + r) * KDIM + k0 + c * 16]);
                cpasync16(sD + 8192 + sw128(r * 128 + c * 16),
                          &g_Bq[(size_t)(bn0 + r) * KDIM + k0 + c * 16]);
            }
        }
        asm volatile("cp.async.commit_group;" ::: "memory");
    };

    // load k32-step fragments (byte addressing; same SW128 layout as fp16 path)
    auto load_frags = [&](uint32_t sB, int kq, uint32_t af[2][4], uint32_t bf[4][2]) {
        #pragma unroll
        for (int mi = 0; mi < 2; mi++) {
            int row = wm * 32 + mi * 16 + aRow;
            uint32_t addr = sB + sw128((uint32_t)(row * 128 + kq * 32 + aKhB));
            asm volatile(
                "ldmatrix.sync.aligned.m8n8.x4.shared.b16 {%0,%1,%2,%3}, [%4];"
                : "=r"(af[mi][0]), "=r"(af[mi][1]), "=r"(af[mi][2]), "=r"(af[mi][3])
                : "r"(addr));
        }
        #pragma unroll
        for (int p = 0; p < 2; p++) {
            int n = wn * 32 + p * 16 + bRowOff;
            uint32_t addr = sB + 8192 + sw128((uint32_t)(n * 128 + kq * 32 + bKhB));
            asm volatile(
                "ldmatrix.sync.aligned.m8n8.x4.shared.b16 {%0,%1,%2,%3}, [%4];"
                : "=r"(bf[p * 2][0]), "=r"(bf[p * 2][1]),
                  "=r"(bf[p * 2 + 1][0]), "=r"(bf[p * 2 + 1][1])
                : "r"(addr));
        }
    };

    issue(0);
    issue(1);

    // stage scales into smem: [kb][row] with stride 66 (bank-spread)
    #pragma unroll
    for (int i = 0; i < 8; i++) {
        int idx = i * 128 + tid;               // 0..1023
        int kb = idx >> 6, rr = idx & 63;
        *reinterpret_cast<float*>(smem + SC_A + (kb * 66 + rr) * 4) =
            g_Asc[(bm0 + rr) * 16 + kb];
        *reinterpret_cast<float*>(smem + SC_B + (kb * 66 + rr) * 4) =
            g_Bsc[(bn0 + rr) * 16 + kb];
    }

    uint32_t afb[2][2][4], bfb[2][4][2];

    #pragma unroll
    for (int it = 0; it < NCH; it++) {
        asm volatile("cp.async.wait_group 1;" ::: "memory");
        __syncthreads();                       // also publishes the scale stage (it==0)
        issue(it + 2);

        uint32_t sB = sbase + (it % STG) * STAGE_BYTES;
        load_frags(sB, 0, afb[0], bfb[0]);

        #pragma unroll
        for (int kq = 0; kq < 4; kq++) {
            int cur = kq & 1;
            if (kq < 3) load_frags(sB, kq + 1, afb[cur ^ 1], bfb[cur ^ 1]);

            int kb = it * 4 + kq;
            float sa[2][2];
            float2 sbv[4];
            #pragma unroll
            for (int mi = 0; mi < 2; mi++) {
                int rr = wm * 32 + mi * 16 + groupID;
                sa[mi][0] = *reinterpret_cast<float*>(smem + SC_A + (kb * 66 + rr) * 4);
                sa[mi][1] = *reinterpret_cast<float*>(smem + SC_A + (kb * 66 + rr + 8) * 4);
            }
            #pragma unroll
            for (int ni = 0; ni < 4; ni++) {
                int cc = wn * 32 + ni * 8 + tig * 2;
                sbv[ni] = *reinterpret_cast<float2*>(smem + SC_B + (kb * 66 + cc) * 4);
            }
            #pragma unroll
            for (int mi = 0; mi < 2; mi++)
                #pragma unroll
                for (int ni = 0; ni < 4; ni++) {
                    int d0, d1, d2, d3;
                    asm volatile(
                        "mma.sync.aligned.m16n8k32.row.col.s32.s8.s8.s32 "
                        "{%0,%1,%2,%3}, {%4,%5,%6,%7}, {%8,%9}, {%10,%11,%12,%13};"
                        : "=r"(d0), "=r"(d1), "=r"(d2), "=r"(d3)
                        : "r"(afb[cur][mi][0]), "r"(afb[cur][mi][1]),
                          "r"(afb[cur][mi][2]), "r"(afb[cur][mi][3]),
                          "r"(bfb[cur][ni][0]), "r"(bfb[cur][ni][1]),
                          "r"(0), "r"(0), "r"(0), "r"(0));
                    acc[mi][ni][0] = fmaf(__int2float_rn(d0), sa[mi][0] * sbv[ni].x, acc[mi][ni][0]);
                    acc[mi][ni][1] = fmaf(__int2float_rn(d1), sa[mi][0] * sbv[ni].y, acc[mi][ni][1]);
                    acc[mi][ni][2] = fmaf(__int2float_rn(d2), sa[mi][1] * sbv[ni].x, acc[mi][ni][2]);
                    acc[mi][ni][3] = fmaf(__int2float_rn(d3), sa[mi][1] * sbv[ni].y, acc[mi][ni][3]);
                }
        }
    }

    #pragma unroll
    for (int mi = 0; mi < 2; mi++) {
        int r0 = bm0 + wm * 32 + mi * 16 + groupID;
        int r1 = r0 + 8;
        float c0 = cpre[mi][0];
        float c1 = cpre[mi][1];
        #pragma unroll
        for (int ni = 0; ni < 4; ni++) {
            int col = bn0 + wn * 32 + ni * 8 + tig * 2;
            float2 v0, v1;
            v0.x = -sqrtf(fmaxf(acc[mi][ni][0] + c0, 0.f));
            v0.y = -sqrtf(fmaxf(acc[mi][ni][1] + c0, 0.f));
            v1.x = -sqrtf(fmaxf(acc[mi][ni][2] + c1, 0.f));
            v1.y = -sqrtf(fmaxf(acc[mi][ni][3] + c1, 0.f));
            *reinterpret_cast<float2*>(out + (size_t)r0 * NNEG + col) = v0;
            *reinterpret_cast<float2*>(out + (size_t)r1 * NNEG + col) = v1;
        }
    }
}

// ---------------------------------------------------------------------------
extern "C" void kernel_launch(void* const* d_in, const int* in_sizes, int n_in,
                              void* d_out, int out_size) {
    const float* head = (const float*)d_in[0];       // (512, 256)
    const float* tail = (const float*)d_in[1];       // (1, 2048, 256)
    const float* rel  = (const float*)d_in[2];       // (1000, 512)
    const int*   rid  = (const int*)d_in[3];         // (512,) int32
    float* out = (float*)d_out;                      // (512, 2048)

    cudaFuncSetAttribute(fused_kernel,
                         cudaFuncAttributeMaxDynamicSharedMemorySize, SM_TOTAL);
    dim3 grid(NNEG / BN, BATCH / BM);                // 32 x 8 = 256 CTAs
    fused_kernel<<<grid, 128, SM_TOTAL>>>(out, head, tail, rel, rid);
}

// round 15
// speedup vs baseline: 1.8243x; 1.8243x over previous
#include <cuda_runtime.h>
#include <cuda_fp16.h>
#include <cstdint>

#define BATCH 512
#define NNEG  2048
#define EDIM  256
#define KDIM  512            // fp16 K = 2*E
#define NCTA  512
#define NTILES 1024          // 32x32 tiles: 16 x 64
#define QSTRIDE (NTILES + NCTA)

// Scratch
__device__ __align__(16) __half g_Ah[BATCH * KDIM];
__device__ __align__(16) __half g_Bh[NNEG  * KDIM];
__device__ float g_c[BATCH];
__device__ unsigned long long g_bar;   // barrier counter (monotonic)
__device__ unsigned long long g_q;     // tile queue counter (monotonic)

#define STAGE_BYTES 16384              // A 2x4K + B 2x4K
#define SM_TOTAL    (3 * STAGE_BYTES)  // 48KB

__device__ __forceinline__ uint32_t s2u(const void* p) {
    uint32_t a;
    asm("{ .reg .u64 t; cvta.to.shared.u64 t, %1; cvt.u32.u64 %0, t; }" : "=r"(a) : "l"(p));
    return a;
}
__device__ __forceinline__ uint32_t sw128(uint32_t off) {
    return off ^ ((off >> 3) & 0x70);
}
__device__ __forceinline__ void cpasync16(uint32_t dst, const void* src) {
    asm volatile("cp.async.cg.shared.global [%0], [%1], 16;" :: "r"(dst), "l"(src));
}
__device__ __forceinline__ float wredsum(float v) {
    #pragma unroll
    for (int o = 16; o > 0; o >>= 1) v += __shfl_xor_sync(0xffffffffu, v, o);
    return v;
}
__device__ __forceinline__ uint4 pack8(const float* v) {
    union { uint4 u; __half2 h[4]; } r;
    r.h[0] = __floats2half2_rn(v[0], v[1]);
    r.h[1] = __floats2half2_rn(v[2], v[3]);
    r.h[2] = __floats2half2_rn(v[4], v[5]);
    r.h[3] = __floats2half2_rn(v[6], v[7]);
    return r.u;
}

// warp-per-row prep helpers (verified R10+)
__device__ __forceinline__ void prep_a_row(int b, int lane,
                                           const float* __restrict__ head,
                                           const float* __restrict__ rel,
                                           const int* __restrict__ rid) {
    int e0 = lane * 8;
    float hv[8];
    *reinterpret_cast<float4*>(hv)     = *reinterpret_cast<const float4*>(&head[b * EDIM + e0]);
    *reinterpret_cast<float4*>(hv + 4) = *reinterpret_cast<const float4*>(&head[b * EDIM + e0 + 4]);
    int r = __ldg(&rid[b]);
    float s = 0.f;
    #pragma unroll
    for (int i = 0; i < 8; i++) s += hv[i] * hv[i];
    s = wredsum(s);
    float inv = 1.f / fmaxf(sqrtf(s), 1e-12f);

    const float* rrow = rel + (size_t)r * KDIM;
    float rh[8], rt[8];
    *reinterpret_cast<float4*>(rh)     = *reinterpret_cast<const float4*>(&rrow[e0]);
    *reinterpret_cast<float4*>(rh + 4) = *reinterpret_cast<const float4*>(&rrow[e0 + 4]);
    *reinterpret_cast<float4*>(rt)     = *reinterpret_cast<const float4*>(&rrow[EDIM + e0]);
    *reinterpret_cast<float4*>(rt + 4) = *reinterpret_cast<const float4*>(&rrow[EDIM + e0 + 4]);

    float v1[8], v2[8], cs = 0.f;
    #pragma unroll
    for (int i = 0; i < 8; i++) {
        float hh = hv[i] * inv * rh[i];
        v1[i] = rt[i] * rt[i];
        v2[i] = -2.f * rt[i] * hh;
        cs += hh * hh;
    }
    size_t ra = (size_t)b * KDIM;
    *reinterpret_cast<uint4*>(&g_Ah[ra + e0])        = pack8(v1);
    *reinterpret_cast<uint4*>(&g_Ah[ra + EDIM + e0]) = pack8(v2);
    cs = wredsum(cs);
    if (lane == 0) g_c[b] = cs;
}
__device__ __forceinline__ void prep_b_row(int j, int lane,
                                           const float* __restrict__ tail) {
    int e0 = lane * 8;
    float tv[8];
    *reinterpret_cast<float4*>(tv)     = *reinterpret_cast<const float4*>(&tail[j * EDIM + e0]);
    *reinterpret_cast<float4*>(tv + 4) = *reinterpret_cast<const float4*>(&tail[j * EDIM + e0 + 4]);
    float s = 0.f;
    #pragma unroll
    for (int i = 0; i < 8; i++) s += tv[i] * tv[i];
    s = wredsum(s);
    float inv = 1.f / fmaxf(sqrtf(s), 1e-12f);
    float w1[8], w2[8];
    #pragma unroll
    for (int i = 0; i < 8; i++) {
        float tn = tv[i] * inv;
        w1[i] = tn * tn;
        w2[i] = tn;
    }
    size_t rb = (size_t)j * KDIM;
    *reinterpret_cast<uint4*>(&g_Bh[rb + e0])        = pack8(w1);
    *reinterpret_cast<uint4*>(&g_Bh[rb + EDIM + e0]) = pack8(w2);
}

// ---------------------------------------------------------------------------
// Fused: prep -> barrier -> dynamic-queue 32x32-tile HMMA GEMM
// ---------------------------------------------------------------------------
__global__ void __launch_bounds__(128, 4)
fused_kernel(float* __restrict__ out,
             const float* __restrict__ head,
             const float* __restrict__ tail,
             const float* __restrict__ rel,
             const int* __restrict__ rid) {
    extern __shared__ __align__(128) char smem[];
    __shared__ unsigned long long ticket_sh;

    int tid = threadIdx.x;
    int lane = tid & 31;
    int wid = tid >> 5;                // 0..3
    int cta = blockIdx.x;              // 0..511

    // ======== Phase 1: prep (1 A-row + 4 B-rows per CTA) ========
    if (wid == 0) {
        prep_a_row(cta, lane, head, rel, rid);
    } else {
        prep_b_row(cta * 4 + (wid - 1), lane, tail);
        if (wid == 1) prep_b_row(cta * 4 + 3, lane, tail);
    }
    __threadfence();

    // ======== Phase 2: grid barrier (512 arrivals; monotonic gen) ========
    __syncthreads();
    unsigned long long gen;
    if (tid == 0) {
        unsigned long long ticket = atomicAdd(&g_bar, 1ULL);
        gen = ticket >> 9;
        ticket_sh = gen;
        unsigned long long target = (gen + 1) << 9;
        unsigned long long cur;
        do {
            asm volatile("ld.acquire.gpu.global.u64 %0, [%1];"
                         : "=l"(cur) : "l"(&g_bar));
            if (cur >= target) break;
            __nanosleep(64);
        } while (true);
    }
    __syncthreads();
    gen = ticket_sh;
    unsigned long long qbase = gen * (unsigned long long)QSTRIDE;

    // ======== Phase 3: dynamic-queue GEMM ========
    int wm = wid & 1;                  // 2 m-warps x 16 rows
    int wn = wid >> 1;                 // 2 n-warps x 16 cols
    int groupID = lane >> 2;
    int tig = lane & 3;
    uint32_t sbase = s2u(smem);

    int aRow = (lane & 7) + ((lane >> 3) & 1) * 8;
    int aKh  = (lane >> 4) * 8;
    int bRowOff = ((lane >> 4) & 1) * 8 + (lane & 7);
    int bKh     = ((lane >> 3) & 1) * 8;

    for (;;) {
        // fetch a tile (CTA-wide; deterministic consumption NTILES+NCTA/exec)
        __syncthreads();               // also: previous tile fully consumed
        if (tid == 0) {
            ticket_sh = atomicAdd(&g_q, 1ULL) - qbase;
        }
        __syncthreads();
        long long t = (long long)ticket_sh;
        if (t >= NTILES) break;

        int m0 = ((int)t & 15) * 32;   // 16 m-tiles
        int n0 = ((int)t >> 4) * 32;   // 64 n-tiles

        // prefetch epilogue constants
        float c0 = g_c[m0 + wm * 16 + groupID];
        float c1 = g_c[m0 + wm * 16 + groupID + 8];

        float acc[2][4];
        #pragma unroll
        for (int ni = 0; ni < 2; ni++)
            #pragma unroll
            for (int q = 0; q < 4; q++) acc[ni][q] = 0.f;

        auto issue = [&](int ic) {
            if (ic < 4) {
                uint32_t sD = sbase + (ic % 3) * STAGE_BYTES;
                int k0 = ic * 128;
                #pragma unroll
                for (int h = 0; h < 2; h++) {
                    uint32_t aD = sD + h * 4096;
                    uint32_t bD = sD + 8192 + h * 4096;
                    int kh = k0 + h * 64;
                    #pragma unroll
                    for (int i = 0; i < 2; i++) {
                        int idx = i * 128 + tid;       // 0..255
                        int r = idx >> 3, c = idx & 7; // r:0..31
                        cpasync16(aD + sw128(r * 128 + c * 16),
                                  &g_Ah[(size_t)(m0 + r) * KDIM + kh + c * 8]);
                        cpasync16(bD + sw128(r * 128 + c * 16),
                                  &g_Bh[(size_t)(n0 + r) * KDIM + kh + c * 8]);
                    }
                }
            }
            asm volatile("cp.async.commit_group;" ::: "memory");
        };

        issue(0);
        issue(1);

        #pragma unroll
        for (int it = 0; it < 4; it++) {
            asm volatile("cp.async.wait_group 1;" ::: "memory");
            __syncthreads();
            issue(it + 2);

            uint32_t sB = sbase + (it % 3) * STAGE_BYTES;

            #pragma unroll
            for (int kk = 0; kk < 8; kk++) {   // 8 k-steps of 16
                uint32_t aBase = sB + (kk >> 2) * 4096;
                uint32_t bBase = sB + 8192 + (kk >> 2) * 4096;
                int kq = kk & 3;

                uint32_t af[4];
                {
                    int row = wm * 16 + aRow;
                    int kcol = kq * 16 + aKh;
                    uint32_t addr = aBase + sw128((uint32_t)(row * 128 + kcol * 2));
                    asm volatile(
                        "ldmatrix.sync.aligned.m8n8.x4.shared.b16 {%0,%1,%2,%3}, [%4];"
                        : "=r"(af[0]), "=r"(af[1]), "=r"(af[2]), "=r"(af[3])
                        : "r"(addr));
                }
                uint32_t bf[2][2];
                {
                    int n = wn * 16 + bRowOff;
                    int kcol = kq * 16 + bKh;
                    uint32_t addr = bBase + sw128((uint32_t)(n * 128 + kcol * 2));
                    asm volatile(
                        "ldmatrix.sync.aligned.m8n8.x4.shared.b16 {%0,%1,%2,%3}, [%4];"
                        : "=r"(bf[0][0]), "=r"(bf[0][1]),
                          "=r"(bf[1][0]), "=r"(bf[1][1])
                        : "r"(addr));
                }
                #pragma unroll
                for (int ni = 0; ni < 2; ni++) {
                    asm volatile(
                        "mma.sync.aligned.m16n8k16.row.col.f32.f16.f16.f32 "
                        "{%0,%1,%2,%3}, {%4,%5,%6,%7}, {%8,%9}, {%0,%1,%2,%3};"
                        : "+f"(acc[ni][0]), "+f"(acc[ni][1]),
                          "+f"(acc[ni][2]), "+f"(acc[ni][3])
                        : "r"(af[0]), "r"(af[1]), "r"(af[2]), "r"(af[3]),
                          "r"(bf[ni][0]), "r"(bf[ni][1]));
                }
            }
        }

        // epilogue: rows m0+wm*16+{groupID, +8}, cols n0+wn*16+ni*8+tig*2
        int r0 = m0 + wm * 16 + groupID;
        int r1 = r0 + 8;
        #pragma unroll
        for (int ni = 0; ni < 2; ni++) {
            int col = n0 + wn * 16 + ni * 8 + tig * 2;
            float2 v0, v1;
            v0.x = -sqrtf(fmaxf(acc[ni][0] + c0, 0.f));
            v0.y = -sqrtf(fmaxf(acc[ni][1] + c0, 0.f));
            v1.x = -sqrtf(fmaxf(acc[ni][2] + c1, 0.f));
            v1.y = -sqrtf(fmaxf(acc[ni][3] + c1, 0.f));
            *reinterpret_cast<float2*>(out + (size_t)r0 * NNEG + col) = v0;
            *reinterpret_cast<float2*>(out + (size_t)r1 * NNEG + col) = v1;
        }
    }
}

// ---------------------------------------------------------------------------
extern "C" void kernel_launch(void* const* d_in, const int* in_sizes, int n_in,
                              void* d_out, int out_size) {
    const float* head = (const float*)d_in[0];       // (512, 256)
    const float* tail = (const float*)d_in[1];       // (1, 2048, 256)
    const float* rel  = (const float*)d_in[2];       // (1000, 512)
    const int*   rid  = (const int*)d_in[3];         // (512,) int32
    float* out = (float*)d_out;                      // (512, 2048)

    cudaFuncSetAttribute(fused_kernel,
                         cudaFuncAttributeMaxDynamicSharedMemorySize, SM_TOTAL);
    fused_kernel<<<NCTA, 128, SM_TOTAL>>>(out, head, tail, rel, rid);
}

// round 16
// speedup vs baseline: 2.4772x; 1.3579x over previous
#include <cuda_runtime.h>
#include <cuda_fp16.h>
#include <cstdint>

#define BATCH 512
#define NNEG  2048
#define EDIM  256
#define KDIM  512           // pure fp16: K = 2*E
#define KC    128           // fp16 K per outer chunk (2 x 64 sub-slabs)
#define NCH   (KDIM / KC)   // 4 outer chunks
#define STG   3

// Scratch
__device__ __align__(16) __half g_Ah[BATCH * KDIM];
__device__ __align__(16) __half g_Bh[NNEG  * KDIM];
__device__ float g_c[BATCH];
__device__ unsigned long long g_gen;       // generation ticket counter (monotonic)
__device__ unsigned int g_rA[8];           // A-group readiness (32 producers each)
__device__ unsigned int g_rB[32];          // B-group readiness (8 producers each)

#define BM 64
#define BN 64
#define STAGE_BYTES 32768                  // A 16KB + B 16KB
#define SM_TOTAL    (STG * STAGE_BYTES)    // 96KB

__device__ __forceinline__ uint32_t s2u(const void* p) {
    uint32_t a;
    asm("{ .reg .u64 t; cvta.to.shared.u64 t, %1; cvt.u32.u64 %0, t; }" : "=r"(a) : "l"(p));
    return a;
}
__device__ __forceinline__ uint32_t sw128(uint32_t off) {
    return off ^ ((off >> 3) & 0x70);
}
__device__ __forceinline__ void cpasync16(uint32_t dst, const void* src) {
    asm volatile("cp.async.cg.shared.global [%0], [%1], 16;" :: "r"(dst), "l"(src));
}
__device__ __forceinline__ float wredsum(float v) {
    #pragma unroll
    for (int o = 16; o > 0; o >>= 1) v += __shfl_xor_sync(0xffffffffu, v, o);
    return v;
}
__device__ __forceinline__ uint4 pack8(const float* v) {
    union { uint4 u; __half2 h[4]; } r;
    r.h[0] = __floats2half2_rn(v[0], v[1]);
    r.h[1] = __floats2half2_rn(v[2], v[3]);
    r.h[2] = __floats2half2_rn(v[4], v[5]);
    r.h[3] = __floats2half2_rn(v[6], v[7]);
    return r.u;
}
__device__ __forceinline__ unsigned int ld_acq_u32(const unsigned int* p) {
    unsigned int v;
    asm volatile("ld.acquire.gpu.global.u32 %0, [%1];" : "=r"(v) : "l"(p));
    return v;
}

// ---------------------------------------------------------------------------
// Fused kernel: pipelined prep -> per-group readiness -> HMMA GEMM (R12 body)
// ---------------------------------------------------------------------------
__global__ void __launch_bounds__(128, 2)
fused_kernel(float* __restrict__ out,
             const float* __restrict__ head,
             const float* __restrict__ tail,
             const float* __restrict__ rel,
             const int* __restrict__ rid) {
    extern __shared__ __align__(128) char smem[];

    int tid = threadIdx.x;
    int lane = tid & 31;
    int wid = tid >> 5;                        // 0..3
    int bx = blockIdx.x;                       // 0..31 (n-tile)
    int by = blockIdx.y;                       // 0..7  (m-tile)
    int flat = by * 32 + bx;                   // 0..255
    int e0 = lane * 8;

    // ======== Phase 1: pipelined prep (R10/R12, known good) ========
    {
        bool hasA = (wid < 2);
        int b  = flat * 2 + wid;
        int j0 = flat * 8 + wid;
        int j1 = j0 + 4;

        float hv[8];
        int r = 0;
        if (hasA) {
            *reinterpret_cast<float4*>(hv)     = *reinterpret_cast<const float4*>(&head[b * EDIM + e0]);
            *reinterpret_cast<float4*>(hv + 4) = *reinterpret_cast<const float4*>(&head[b * EDIM + e0 + 4]);
            r = __ldg(&rid[b]);
        }
        float tv0[8], tv1[8];
        *reinterpret_cast<float4*>(tv0)     = *reinterpret_cast<const float4*>(&tail[j0 * EDIM + e0]);
        *reinterpret_cast<float4*>(tv0 + 4) = *reinterpret_cast<const float4*>(&tail[j0 * EDIM + e0 + 4]);
        *reinterpret_cast<float4*>(tv1)     = *reinterpret_cast<const float4*>(&tail[j1 * EDIM + e0]);
        *reinterpret_cast<float4*>(tv1 + 4) = *reinterpret_cast<const float4*>(&tail[j1 * EDIM + e0 + 4]);

        float rh[8], rt[8];
        if (hasA) {
            const float* rrow = rel + (size_t)r * KDIM;
            *reinterpret_cast<float4*>(rh)     = *reinterpret_cast<const float4*>(&rrow[e0]);
            *reinterpret_cast<float4*>(rh + 4) = *reinterpret_cast<const float4*>(&rrow[e0 + 4]);
            *reinterpret_cast<float4*>(rt)     = *reinterpret_cast<const float4*>(&rrow[EDIM + e0]);
            *reinterpret_cast<float4*>(rt + 4) = *reinterpret_cast<const float4*>(&rrow[EDIM + e0 + 4]);
        }
        {
            float s = 0.f;
            #pragma unroll
            for (int i = 0; i < 8; i++) s += tv0[i] * tv0[i];
            s = wredsum(s);
            float inv = 1.f / fmaxf(sqrtf(s), 1e-12f);
            float w1[8], w2[8];
            #pragma unroll
            for (int i = 0; i < 8; i++) {
                float tn = tv0[i] * inv;
                w1[i] = tn * tn;
                w2[i] = tn;
            }
            size_t rb = (size_t)j0 * KDIM;
            *reinterpret_cast<uint4*>(&g_Bh[rb + e0])        = pack8(w1);
            *reinterpret_cast<uint4*>(&g_Bh[rb + EDIM + e0]) = pack8(w2);
        }
        {
            float s = 0.f;
            #pragma unroll
            for (int i = 0; i < 8; i++) s += tv1[i] * tv1[i];
            s = wredsum(s);
            float inv = 1.f / fmaxf(sqrtf(s), 1e-12f);
            float w1[8], w2[8];
            #pragma unroll
            for (int i = 0; i < 8; i++) {
                float tn = tv1[i] * inv;
                w1[i] = tn * tn;
                w2[i] = tn;
            }
            size_t rb = (size_t)j1 * KDIM;
            *reinterpret_cast<uint4*>(&g_Bh[rb + e0])        = pack8(w1);
            *reinterpret_cast<uint4*>(&g_Bh[rb + EDIM + e0]) = pack8(w2);
        }
        if (hasA) {
            float s = 0.f;
            #pragma unroll
            for (int i = 0; i < 8; i++) s += hv[i] * hv[i];
            s = wredsum(s);
            float inv = 1.f / fmaxf(sqrtf(s), 1e-12f);
            float v1[8], v2[8], cs = 0.f;
            #pragma unroll
            for (int i = 0; i < 8; i++) {
                float hh = hv[i] * inv * rh[i];
                v1[i] = rt[i] * rt[i];
                v2[i] = -2.f * rt[i] * hh;
                cs += hh * hh;
            }
            size_t ra = (size_t)b * KDIM;
            *reinterpret_cast<uint4*>(&g_Ah[ra + e0])        = pack8(v1);
            *reinterpret_cast<uint4*>(&g_Ah[ra + EDIM + e0]) = pack8(v2);
            cs = wredsum(cs);
            if (lane == 0) g_c[b] = cs;
        }
    }
    __threadfence();

    // ======== Phase 2: per-group readiness (replaces full grid barrier) ====
    // Producer flat contributes to A-group flat/32 (== by) and B-group flat/8.
    // Consumer (bx, by) needs A-group by (32 arrivals) and B-group bx (8).
    __syncthreads();
    if (tid == 0) {
        unsigned long long ticket = atomicAdd(&g_gen, 1ULL);
        unsigned long long gen = ticket >> 8;          // 256 tickets per launch
        atomicAdd(&g_rA[flat >> 5], 1u);
        atomicAdd(&g_rB[flat >> 3], 1u);
        unsigned int tgtA = (unsigned int)((gen + 1) * 32);
        unsigned int tgtB = (unsigned int)((gen + 1) * 8);
        while ((int)(ld_acq_u32(&g_rA[by]) - tgtA) < 0) __nanosleep(32);
        while ((int)(ld_acq_u32(&g_rB[bx]) - tgtB) < 0) __nanosleep(32);
    }
    __syncthreads();

    // ======== Phase 3: GEMM (R12 body, unchanged) ========
    int wm = wid & 1;
    int wn = wid >> 1;
    int bn0 = bx * BN;
    int bm0 = by * BM;
    int groupID = lane >> 2;
    int tig = lane & 3;

    uint32_t sbase = s2u(smem);

    int aRow = (lane & 7) + ((lane >> 3) & 1) * 8;
    int aKh  = (lane >> 4) * 8;
    int bRowOff = ((lane >> 4) & 1) * 8 + (lane & 7);
    int bKh     = ((lane >> 3) & 1) * 8;

    auto issue = [&](int ic) {
        if (ic < NCH) {
            uint32_t sD = sbase + (ic % STG) * STAGE_BYTES;
            int k0 = ic * KC;
            #pragma unroll
            for (int h = 0; h < 2; h++) {
                uint32_t aD = sD + h * 8192;
                uint32_t bD = sD + 16384 + h * 8192;
                int kh = k0 + h * 64;
                #pragma unroll
                for (int i = 0; i < 4; i++) {
                    int idx = i * 128 + tid;
                    int r = idx >> 3, c = idx & 7;
                    cpasync16(aD + sw128(r * 128 + c * 16),
                              &g_Ah[(size_t)(bm0 + r) * KDIM + kh + c * 8]);
                    cpasync16(bD + sw128(r * 128 + c * 16),
                              &g_Bh[(size_t)(bn0 + r) * KDIM + kh + c * 8]);
                }
            }
        }
        asm volatile("cp.async.commit_group;" ::: "memory");
    };

    issue(0);
    issue(1);

    // epilogue constants (A producers for this m-block are done per rA wait)
    int er0 = bm0 + wm * 32 + groupID;
    float cpre[2][2];
    cpre[0][0] = g_c[er0];
    cpre[0][1] = g_c[er0 + 8];
    cpre[1][0] = g_c[er0 + 16];
    cpre[1][1] = g_c[er0 + 24];

    float acc[2][4][4];
    #pragma unroll
    for (int mi = 0; mi < 2; mi++)
        #pragma unroll
        for (int ni = 0; ni < 4; ni++)
            #pragma unroll
            for (int q = 0; q < 4; q++) acc[mi][ni][q] = 0.f;

    auto load_frags = [&](uint32_t sB, int kk, uint32_t af[2][4], uint32_t bf[4][2]) {
        uint32_t aBase = sB + (kk >> 2) * 8192;
        uint32_t bBase = sB + 16384 + (kk >> 2) * 8192;
        int kq = kk & 3;
        #pragma unroll
        for (int mi = 0; mi < 2; mi++) {
            int row = wm * 32 + mi * 16 + aRow;
            int kcol = kq * 16 + aKh;
            uint32_t addr = aBase + sw128((uint32_t)(row * 128 + kcol * 2));
            asm volatile(
                "ldmatrix.sync.aligned.m8n8.x4.shared.b16 {%0,%1,%2,%3}, [%4];"
                : "=r"(af[mi][0]), "=r"(af[mi][1]), "=r"(af[mi][2]), "=r"(af[mi][3])
                : "r"(addr));
        }
        #pragma unroll
        for (int p = 0; p < 2; p++) {
            int n = wn * 32 + p * 16 + bRowOff;
            int kcol = kq * 16 + bKh;
            uint32_t addr = bBase + sw128((uint32_t)(n * 128 + kcol * 2));
            asm volatile(
                "ldmatrix.sync.aligned.m8n8.x4.shared.b16 {%0,%1,%2,%3}, [%4];"
                : "=r"(bf[p * 2][0]), "=r"(bf[p * 2][1]),
                  "=r"(bf[p * 2 + 1][0]), "=r"(bf[p * 2 + 1][1])
                : "r"(addr));
        }
    };

    auto do_mmas = [&](uint32_t af[2][4], uint32_t bf[4][2]) {
        #pragma unroll
        for (int mi = 0; mi < 2; mi++)
            #pragma unroll
            for (int ni = 0; ni < 4; ni++) {
                asm volatile(
                    "mma.sync.aligned.m16n8k16.row.col.f32.f16.f16.f32 "
                    "{%0,%1,%2,%3}, {%4,%5,%6,%7}, {%8,%9}, {%0,%1,%2,%3};"
                    : "+f"(acc[mi][ni][0]), "+f"(acc[mi][ni][1]),
                      "+f"(acc[mi][ni][2]), "+f"(acc[mi][ni][3])
                    : "r"(af[mi][0]), "r"(af[mi][1]), "r"(af[mi][2]), "r"(af[mi][3]),
                      "r"(bf[ni][0]), "r"(bf[ni][1]));
            }
    };

    uint32_t afb[2][2][4], bfb[2][4][2];    // double-buffered fragments

    #pragma unroll
    for (int it = 0; it < NCH; it++) {
        asm volatile("cp.async.wait_group 1;" ::: "memory");
        __syncthreads();
        issue(it + 2);

        uint32_t sB = sbase + (it % STG) * STAGE_BYTES;

        load_frags(sB, 0, afb[0], bfb[0]);
        #pragma unroll
        for (int kk = 0; kk < 8; kk++) {
            int cur = kk & 1;
            if (kk < 7) load_frags(sB, kk + 1, afb[cur ^ 1], bfb[cur ^ 1]);
            do_mmas(afb[cur], bfb[cur]);
        }
    }

    #pragma unroll
    for (int mi = 0; mi < 2; mi++) {
        int r0 = bm0 + wm * 32 + mi * 16 + groupID;
        int r1 = r0 + 8;
        float c0 = cpre[mi][0];
        float c1 = cpre[mi][1];
        #pragma unroll
        for (int ni = 0; ni < 4; ni++) {
            int col = bn0 + wn * 32 + ni * 8 + tig * 2;
            float2 v0, v1;
            v0.x = -sqrtf(fmaxf(acc[mi][ni][0] + c0, 0.f));
            v0.y = -sqrtf(fmaxf(acc[mi][ni][1] + c0, 0.f));
            v1.x = -sqrtf(fmaxf(acc[mi][ni][2] + c1, 0.f));
            v1.y = -sqrtf(fmaxf(acc[mi][ni][3] + c1, 0.f));
            *reinterpret_cast<float2*>(out + (size_t)r0 * NNEG + col) = v0;
            *reinterpret_cast<float2*>(out + (size_t)r1 * NNEG + col) = v1;
        }
    }
}

// ---------------------------------------------------------------------------
extern "C" void kernel_launch(void* const* d_in, const int* in_sizes, int n_in,
                              void* d_out, int out_size) {
    const float* head = (const float*)d_in[0];       // (512, 256)
    const float* tail = (const float*)d_in[1];       // (1, 2048, 256)
    const float* rel  = (const float*)d_in[2];       // (1000, 512)
    const int*   rid  = (const int*)d_in[3];         // (512,) int32
    float* out = (float*)d_out;                      // (512, 2048)

    cudaFuncSetAttribute(fused_kernel,
                         cudaFuncAttributeMaxDynamicSharedMemorySize, SM_TOTAL);
    dim3 grid(NNEG / BN, BATCH / BM);                // 32 x 8 = 256 CTAs
    fused_kernel<<<grid, 128, SM_TOTAL>>>(out, head, tail, rel, rid);
}